// round 2
// baseline (speedup 1.0000x reference)
#include <cuda_runtime.h>
#include <cuda_bf16.h>
#include <math_constants.h>

#define Bsz 1024
#define Ssz 128
#define NW (Bsz*Ssz)   // 131072 words

// scratch (static device allocations are allowed)
__device__ float g_xg[2][(size_t)NW*24];  // pre-activations Wih@x + b, per direction
__device__ float g_h[(size_t)NW*12];      // bi-LSTM hidden output [B,S,2H]

__device__ __forceinline__ float sigmoidf_(float x){ return 1.f/(1.f+__expf(-x)); }
__device__ __forceinline__ float tanh_fast(float x){ float y; asm("tanh.approx.f32 %0, %1;" : "=f"(y) : "f"(x)); return y; }

// ---------------- Kernel 1: char-CNN + embeddings + xgate precompute ----------------
__global__ __launch_bounds__(256) void k1_embed(
    const int* __restrict__ word_idx, const int* __restrict__ char_idx,
    const float* __restrict__ word_emb, const float* __restrict__ char_emb,
    const float* __restrict__ Wc, const float* __restrict__ bc,
    const float* __restrict__ Wih_f, const float* __restrict__ b_f,
    const float* __restrict__ Wih_b, const float* __restrict__ b_b)
{
    __shared__ float s_ce[600];
    __shared__ float s_Wc[72];
    __shared__ float s_bc[4];
    __shared__ float s_Wf[336], s_bf[24], s_Wb[336], s_bb[24];
    int tid = threadIdx.x;
    for (int i=tid;i<600;i+=256) s_ce[i]=char_emb[i];
    for (int i=tid;i<72;i+=256)  s_Wc[i]=Wc[i];
    if (tid<4) s_bc[tid]=bc[tid];
    for (int i=tid;i<336;i+=256){ s_Wf[i]=Wih_f[i]; s_Wb[i]=Wih_b[i]; }
    if (tid<24){ s_bf[tid]=b_f[tid]; s_bb[tid]=b_b[tid]; }
    __syncthreads();

    int w = blockIdx.x*256 + tid;          // exact grid, always valid
    float x[14];
    int widx = word_idx[w];
    const float2* wep = (const float2*)(word_emb) + (size_t)widx*5;
    #pragma unroll
    for (int k=0;k<5;k++){ float2 v = __ldg(wep+k); x[2*k]=v.x; x[2*k+1]=v.y; }

    int ci[14];
    const int* cp = char_idx + (size_t)w*14;
    #pragma unroll
    for (int k=0;k<14;k++) ci[k]=__ldg(cp+k);

    // rolling 3-char window, 4 filters, max-pool over 12 windows
    float e[18];
    #pragma unroll
    for (int m=0;m<6;m++){ e[m]=s_ce[ci[0]*6+m]; e[6+m]=s_ce[ci[1]*6+m]; }
    float a0=-CUDART_INF_F,a1=-CUDART_INF_F,a2=-CUDART_INF_F,a3=-CUDART_INF_F;
    #pragma unroll
    for (int win=0;win<12;win++){
        #pragma unroll
        for (int m=0;m<6;m++) e[12+m]=s_ce[ci[win+2]*6+m];
        float p0=s_bc[0],p1=s_bc[1],p2=s_bc[2],p3=s_bc[3];
        #pragma unroll
        for (int m=0;m<18;m++){
            float v=e[m];
            p0 = fmaf(v, s_Wc[0*18+m], p0);
            p1 = fmaf(v, s_Wc[1*18+m], p1);
            p2 = fmaf(v, s_Wc[2*18+m], p2);
            p3 = fmaf(v, s_Wc[3*18+m], p3);
        }
        a0=fmaxf(a0,p0); a1=fmaxf(a1,p1); a2=fmaxf(a2,p2); a3=fmaxf(a3,p3);
        #pragma unroll
        for (int m=0;m<12;m++) e[m]=e[m+6];
    }
    x[10]=a0; x[11]=a1; x[12]=a2; x[13]=a3;

    // xgate forward
    float xg[24];
    #pragma unroll
    for (int g=0; g<24; g++){
        float acc = s_bf[g];
        #pragma unroll
        for (int k=0;k<14;k++) acc = fmaf(x[k], s_Wf[g*14+k], acc);
        xg[g]=acc;
    }
    float4* of = (float4*)(&g_xg[0][(size_t)w*24]);
    #pragma unroll
    for (int q=0;q<6;q++) of[q] = make_float4(xg[4*q],xg[4*q+1],xg[4*q+2],xg[4*q+3]);
    // xgate backward
    #pragma unroll
    for (int g=0; g<24; g++){
        float acc = s_bb[g];
        #pragma unroll
        for (int k=0;k<14;k++) acc = fmaf(x[k], s_Wb[g*14+k], acc);
        xg[g]=acc;
    }
    float4* ob = (float4*)(&g_xg[1][(size_t)w*24]);
    #pragma unroll
    for (int q=0;q<6;q++) ob[q] = make_float4(xg[4*q],xg[4*q+1],xg[4*q+2],xg[4*q+3]);
}

// ---------------- Kernel 2: bidirectional LSTM recurrence ----------------
// one warp per (sentence, direction). lane j < 24 owns gate j (torch order i,f,g,o).
__global__ __launch_bounds__(256) void k2_lstm(
    const float* __restrict__ Whh_f, const float* __restrict__ Whh_b)
{
    const unsigned FULL = 0xffffffffu;
    int wg   = (blockIdx.x*256 + threadIdx.x) >> 5;   // 0..2047
    int lane = threadIdx.x & 31;
    int b    = wg >> 1;
    int dir  = wg & 1;
    int jc   = (lane < 24) ? lane : 0;
    int gl   = (lane < 6) ? lane : 0;
    bool is_g = (lane >= 12 && lane < 18);

    const float* Whh = dir ? Whh_b : Whh_f;
    float w0=__ldg(Whh+jc*6+0), w1=__ldg(Whh+jc*6+1), w2=__ldg(Whh+jc*6+2),
          w3=__ldg(Whh+jc*6+3), w4=__ldg(Whh+jc*6+4), w5=__ldg(Whh+jc*6+5);

    const float* xg = g_xg[dir] + (size_t)b*Ssz*24;
    float* hout = g_h + (size_t)b*Ssz*12 + dir*6;

    float h0=0.f,h1=0.f,h2=0.f,h3=0.f,h4=0.f,h5=0.f,c=0.f;
    int s  = dir ? (Ssz-1) : 0;
    int ds = dir ? -1 : 1;

    float gx = __ldg(xg + s*24 + jc);  // prefetched pre-activation
    for (int t=0; t<Ssz; t++){
        float gcur = gx;
        int sn = s + ds;
        if (t+1 < Ssz) gx = __ldg(xg + sn*24 + jc);  // prefetch next step

        float g = fmaf(w0,h0,gcur);
        g = fmaf(w1,h1,g); g = fmaf(w2,h2,g); g = fmaf(w3,h3,g);
        g = fmaf(w4,h4,g); g = fmaf(w5,h5,g);
        float act = is_g ? tanh_fast(g) : sigmoidf_(g);

        float ai = __shfl_sync(FULL, act, gl);
        float af = __shfl_sync(FULL, act, gl+6);
        float ag = __shfl_sync(FULL, act, gl+12);
        float ao = __shfl_sync(FULL, act, gl+18);
        c = fmaf(af, c, ai*ag);
        float hj = ao * tanh_fast(c);

        h0=__shfl_sync(FULL,hj,0); h1=__shfl_sync(FULL,hj,1); h2=__shfl_sync(FULL,hj,2);
        h3=__shfl_sync(FULL,hj,3); h4=__shfl_sync(FULL,hj,4); h5=__shfl_sync(FULL,hj,5);

        if (lane < 6) hout[s*12 + lane] = hj;
        s = sn;
    }
}

// ---------------- Kernel 3: tag linear + log_softmax ----------------
// warp per (b,s) pair, 16 pairs per warp to amortize the shared Wt load.
__global__ __launch_bounds__(256) void k3_tag(
    const float* __restrict__ Wt, const float* __restrict__ bt, float* __restrict__ out)
{
    __shared__ float sW[12*136];   // transposed + padded: sW[k*136 + j], conflict-free
    __shared__ float sb[136];
    int tid = threadIdx.x;
    for (int i=tid;i<1620;i+=256){ int j=i/12, k=i%12; sW[k*136+j]=Wt[i]; }
    if (tid<135) sb[tid]=bt[tid];
    __syncthreads();

    int warp = tid>>5, lane = tid&31;
    int base = (blockIdx.x*8 + warp)*16;
    for (int it=0; it<16; it++){
        int p = base + it;
        const float* hp = g_h + (size_t)p*12;
        float h[12];
        #pragma unroll
        for (int k=0;k<12;k++) h[k]=__ldg(hp+k);

        float tg[5];
        float m = -CUDART_INF_F;
        #pragma unroll
        for (int t5=0;t5<5;t5++){
            int j = lane + 32*t5;
            float v = -CUDART_INF_F;
            if (j < 135){
                v = sb[j];
                #pragma unroll
                for (int k=0;k<12;k++) v = fmaf(h[k], sW[k*136+j], v);
            }
            tg[t5]=v; m=fmaxf(m,v);
        }
        #pragma unroll
        for (int o=16;o>0;o>>=1) m = fmaxf(m, __shfl_xor_sync(0xffffffffu,m,o));
        float zs = 0.f;
        #pragma unroll
        for (int t5=0;t5<5;t5++){ int j=lane+32*t5; if (j<135) zs += __expf(tg[t5]-m); }
        #pragma unroll
        for (int o=16;o>0;o>>=1) zs += __shfl_xor_sync(0xffffffffu,zs,o);
        float lse = m + __logf(zs);
        float* op = out + (size_t)p*135;
        #pragma unroll
        for (int t5=0;t5<5;t5++){ int j=lane+32*t5; if (j<135) op[j]=tg[t5]-lse; }
    }
}

// ---------------- Launch ----------------
extern "C" void kernel_launch(void* const* d_in, const int* in_sizes, int n_in,
                              void* d_out, int out_size)
{
    // Bind inputs by element count (robust to metadata ordering; forward comes
    // before backward for the duplicated sizes in both plausible orderings).
    const int *word_idx=nullptr,*char_idx=nullptr;
    const float *word_emb=nullptr,*char_emb=nullptr,*Wc=nullptr,*bc=nullptr,
        *Wih_f=nullptr,*Whh_f=nullptr,*b_f=nullptr,
        *Wih_b=nullptr,*Whh_b=nullptr,*b_b=nullptr,*Wt=nullptr,*bt=nullptr;
    for (int i=0;i<n_in;i++){
        int sz = in_sizes[i]; const void* p = d_in[i];
        switch (sz){
            case 131072:  word_idx=(const int*)p; break;          // [B,S]
            case 1835008: char_idx=(const int*)p; break;          // [B,S,LP]
            case 500000:  word_emb=(const float*)p; break;        // [V,WE]
            case 600:     char_emb=(const float*)p; break;        // [A,CE]
            case 72:      Wc=(const float*)p; break;              // [Lf,K*CE]
            case 4:       bc=(const float*)p; break;              // [Lf]
            case 336:     if(!Wih_f) Wih_f=(const float*)p; else Wih_b=(const float*)p; break;
            case 144:     if(!Whh_f) Whh_f=(const float*)p; else Whh_b=(const float*)p; break;
            case 24:      if(!b_f)   b_f  =(const float*)p; else b_b  =(const float*)p; break;
            case 1620:    Wt=(const float*)p; break;              // [T,2H]
            case 135:     bt=(const float*)p; break;              // [T]
        }
    }

    k1_embed<<<NW/256, 256>>>(word_idx, char_idx, word_emb, char_emb,
                              Wc, bc, Wih_f, b_f, Wih_b, b_b);
    k2_lstm<<<(2*Bsz*32)/256, 256>>>(Whh_f, Whh_b);   // 2048 warps
    k3_tag<<<NW/128, 256>>>(Wt, bt, (float*)d_out);
    (void)out_size; (void)n_in;
}

// round 3
// speedup vs baseline: 1.1995x; 1.1995x over previous
#include <cuda_runtime.h>
#include <cuda_bf16.h>
#include <math_constants.h>

#define Bsz 1024
#define Ssz 128
#define NW (Bsz*Ssz)   // 131072 words

// scratch (static device allocations are allowed)
__device__ float g_xg[2][(size_t)NW*24];  // pre-activations Wih@x + b, per direction
__device__ float g_h[(size_t)NW*12];      // bi-LSTM hidden output [B,S,2H]

__device__ __forceinline__ float tanh_fast(float x){ float y; asm("tanh.approx.f32 %0, %1;" : "=f"(y) : "f"(x)); return y; }

// ---------------- Kernel 1: char-CNN (table-factored) + embeddings + xgate precompute ----
__global__ __launch_bounds__(256) void k1_embed(
    const int* __restrict__ word_idx, const int* __restrict__ char_idx,
    const float* __restrict__ word_emb, const float* __restrict__ char_emb,
    const float* __restrict__ Wc, const float* __restrict__ bc,
    const float* __restrict__ Wih_f, const float* __restrict__ b_f,
    const float* __restrict__ Wih_b, const float* __restrict__ b_b)
{
    __shared__ float4 sP[300];    // P[c][k] : 4-filter partial dots, bias folded into k=0
    __shared__ float4 sW[192];    // [48 gates][4 float4]  (14-wide rows zero-padded to 16)
    __shared__ float  sB[48];
    int tid = threadIdx.x;

    // build P[c][k][l] = sum_m ce[c][m] * Wc[l][k*6+m]  (+ bc[l] when k==0)
    for (int i = tid; i < 300; i += 256){
        int c = i/3, k = i%3;
        float4 acc;
        if (k==0){ acc.x=__ldg(bc+0); acc.y=__ldg(bc+1); acc.z=__ldg(bc+2); acc.w=__ldg(bc+3); }
        else     { acc.x=0.f; acc.y=0.f; acc.z=0.f; acc.w=0.f; }
        #pragma unroll
        for (int m=0;m<6;m++){
            float e = __ldg(char_emb + c*6 + m);
            acc.x = fmaf(e, __ldg(Wc + 0*18 + k*6 + m), acc.x);
            acc.y = fmaf(e, __ldg(Wc + 1*18 + k*6 + m), acc.y);
            acc.z = fmaf(e, __ldg(Wc + 2*18 + k*6 + m), acc.z);
            acc.w = fmaf(e, __ldg(Wc + 3*18 + k*6 + m), acc.w);
        }
        sP[i] = acc;
    }
    // build padded gate weights: gate g<24 = forward, g>=24 = backward
    if (tid < 192){
        int g = tid >> 2, q = tid & 3;
        const float* Wih = (g < 24) ? (Wih_f + g*14) : (Wih_b + (g-24)*14);
        int base = q*4;
        float4 wv;
        wv.x = (base+0 < 14) ? __ldg(Wih+base+0) : 0.f;
        wv.y = (base+1 < 14) ? __ldg(Wih+base+1) : 0.f;
        wv.z = (base+2 < 14) ? __ldg(Wih+base+2) : 0.f;
        wv.w = (base+3 < 14) ? __ldg(Wih+base+3) : 0.f;
        sW[tid] = wv;
    }
    if (tid < 48) sB[tid] = (tid < 24) ? __ldg(b_f + tid) : __ldg(b_b + tid - 24);
    __syncthreads();

    int w = blockIdx.x*256 + tid;   // exact grid

    // char ids (int2-aligned: w*14*4 % 8 == 0)
    int ci[14];
    const int2* cp = (const int2*)(char_idx + (size_t)w*14);
    #pragma unroll
    for (int k=0;k<7;k++){ int2 v = __ldg(cp+k); ci[2*k]=v.x; ci[2*k+1]=v.y; }

    // conv + maxpool: window w = P[c0][0] + P[c1][1] + P[c2][2]
    float4 a = make_float4(-CUDART_INF_F,-CUDART_INF_F,-CUDART_INF_F,-CUDART_INF_F);
    #pragma unroll
    for (int win=0; win<12; win++){
        float4 s0 = sP[ci[win]  *3 + 0];
        float4 s1 = sP[ci[win+1]*3 + 1];
        float4 s2 = sP[ci[win+2]*3 + 2];
        float px = s0.x + s1.x + s2.x;
        float py = s0.y + s1.y + s2.y;
        float pz = s0.z + s1.z + s2.z;
        float pw = s0.w + s1.w + s2.w;
        a.x = fmaxf(a.x, px); a.y = fmaxf(a.y, py);
        a.z = fmaxf(a.z, pz); a.w = fmaxf(a.w, pw);
    }

    // x vector (padded to 16)
    float x[16];
    int widx = __ldg(word_idx + w);
    const float2* wep = (const float2*)(word_emb) + (size_t)widx*5;
    #pragma unroll
    for (int k=0;k<5;k++){ float2 v = __ldg(wep+k); x[2*k]=v.x; x[2*k+1]=v.y; }
    x[10]=a.x; x[11]=a.y; x[12]=a.z; x[13]=a.w; x[14]=0.f; x[15]=0.f;

    // 48 gate pre-activations, 4 at a time -> float4 stores
    float4* outf = (float4*)(&g_xg[0][(size_t)w*24]);
    float4* outb = (float4*)(&g_xg[1][(size_t)w*24]);
    #pragma unroll
    for (int g4=0; g4<12; g4++){
        float r[4];
        #pragma unroll
        for (int u=0; u<4; u++){
            int g = g4*4 + u;
            float acc = sB[g];
            #pragma unroll
            for (int q=0; q<4; q++){
                float4 wv = sW[g*4 + q];
                acc = fmaf(x[4*q+0], wv.x, acc);
                acc = fmaf(x[4*q+1], wv.y, acc);
                acc = fmaf(x[4*q+2], wv.z, acc);
                acc = fmaf(x[4*q+3], wv.w, acc);
            }
            r[u] = acc;
        }
        float4 rv = make_float4(r[0],r[1],r[2],r[3]);
        if (g4 < 6) outf[g4] = rv; else outb[g4-6] = rv;
    }
}

// ---------------- Kernel 2: bidirectional LSTM recurrence ----------------
// one warp per (sentence, direction). lane j < 24 owns gate j (torch order i,f,g,o).
__global__ __launch_bounds__(256) void k2_lstm(
    const float* __restrict__ Whh_f, const float* __restrict__ Whh_b)
{
    const unsigned FULL = 0xffffffffu;
    int wg   = (blockIdx.x*256 + threadIdx.x) >> 5;   // 0..2047
    int lane = threadIdx.x & 31;
    int b    = wg >> 1;
    int dir  = wg & 1;
    int jc   = (lane < 24) ? lane : 0;
    bool is_g = (lane >= 12 && lane < 18);
    float sm = is_g ? 1.f : 0.5f;     // sigmoid(x) = 0.5*tanh(0.5x)+0.5
    float ab = is_g ? 0.f : 0.5f;

    const float* Whh = dir ? Whh_b : Whh_f;
    float w0=__ldg(Whh+jc*6+0), w1=__ldg(Whh+jc*6+1), w2=__ldg(Whh+jc*6+2),
          w3=__ldg(Whh+jc*6+3), w4=__ldg(Whh+jc*6+4), w5=__ldg(Whh+jc*6+5);

    const float* xg = g_xg[dir] + (size_t)b*Ssz*24;
    float* hout = g_h + (size_t)b*Ssz*12 + dir*6;

    float h0=0.f,h1=0.f,h2=0.f,h3=0.f,h4=0.f,h5=0.f,c=0.f;
    int s  = dir ? (Ssz-1) : 0;
    int ds = dir ? -1 : 1;

    float gx = __ldg(xg + s*24 + jc);  // prefetched pre-activation
    #pragma unroll 2
    for (int t=0; t<Ssz; t++){
        float gcur = gx;
        int sn = s + ds;
        if (t+1 < Ssz) gx = __ldg(xg + sn*24 + jc);  // prefetch next step

        float g = fmaf(w0,h0,gcur);
        g = fmaf(w1,h1,g); g = fmaf(w2,h2,g); g = fmaf(w3,h3,g);
        g = fmaf(w4,h4,g); g = fmaf(w5,h5,g);
        float act = fmaf(sm, tanh_fast(g*sm), ab);   // tanh for g-gate, sigmoid otherwise

        // lanes 0-5: act is their own i-gate; gather f,g,o
        float af = __shfl_sync(FULL, act, lane+6);
        float ag = __shfl_sync(FULL, act, lane+12);
        float ao = __shfl_sync(FULL, act, lane+18);
        c = fmaf(af, c, act*ag);
        float hj = ao * tanh_fast(c);

        h0=__shfl_sync(FULL,hj,0); h1=__shfl_sync(FULL,hj,1); h2=__shfl_sync(FULL,hj,2);
        h3=__shfl_sync(FULL,hj,3); h4=__shfl_sync(FULL,hj,4); h5=__shfl_sync(FULL,hj,5);

        if (lane < 6) hout[s*12 + lane] = hj;
        s = sn;
    }
}

// ---------------- Kernel 3: tag linear + log_softmax (weights in registers) --------
// warp per 16 (b,s) pairs; each thread owns 5 tag columns kept in registers.
__global__ __launch_bounds__(256) void k3_tag(
    const float* __restrict__ Wt, const float* __restrict__ bt, float* __restrict__ out)
{
    int tid = threadIdx.x, lane = tid & 31, warp = tid >> 5;

    float w[5][12], bs[5];
    #pragma unroll
    for (int t5=0; t5<5; t5++){
        int j = lane + 32*t5;
        bool valid = (j < 135);
        bs[t5] = valid ? __ldg(bt + j) : -1e30f;   // exp(-1e30)=0, drops out of sum
        #pragma unroll
        for (int k=0;k<12;k++) w[t5][k] = valid ? __ldg(Wt + j*12 + k) : 0.f;
    }

    int base = (blockIdx.x*8 + warp)*16;
    for (int it=0; it<16; it++){
        int p = base + it;
        const float4* hp = (const float4*)(g_h + (size_t)p*12);  // 48B stride, 16B aligned
        float4 h0 = __ldg(hp+0), h1 = __ldg(hp+1), h2 = __ldg(hp+2);
        float h[12] = {h0.x,h0.y,h0.z,h0.w, h1.x,h1.y,h1.z,h1.w, h2.x,h2.y,h2.z,h2.w};

        // |v| is bounded (|h|<1, small weights): safe to skip the max-shift
        float tg[5]; float zs = 0.f;
        #pragma unroll
        for (int t5=0; t5<5; t5++){
            float v = bs[t5];
            #pragma unroll
            for (int k=0;k<12;k++) v = fmaf(h[k], w[t5][k], v);
            tg[t5] = v;
            zs += __expf(v);
        }
        #pragma unroll
        for (int o=16;o>0;o>>=1) zs += __shfl_xor_sync(0xffffffffu, zs, o);
        float lse = __logf(zs);

        float* op = out + (size_t)p*135;
        #pragma unroll
        for (int t5=0; t5<5; t5++){
            int j = lane + 32*t5;
            if (j < 135) op[j] = tg[t5] - lse;
        }
    }
}

// ---------------- Launch ----------------
extern "C" void kernel_launch(void* const* d_in, const int* in_sizes, int n_in,
                              void* d_out, int out_size)
{
    const int *word_idx=nullptr,*char_idx=nullptr;
    const float *word_emb=nullptr,*char_emb=nullptr,*Wc=nullptr,*bc=nullptr,
        *Wih_f=nullptr,*Whh_f=nullptr,*b_f=nullptr,
        *Wih_b=nullptr,*Whh_b=nullptr,*b_b=nullptr,*Wt=nullptr,*bt=nullptr;
    for (int i=0;i<n_in;i++){
        int sz = in_sizes[i]; const void* p = d_in[i];
        switch (sz){
            case 131072:  word_idx=(const int*)p; break;          // [B,S]
            case 1835008: char_idx=(const int*)p; break;          // [B,S,LP]
            case 500000:  word_emb=(const float*)p; break;        // [V,WE]
            case 600:     char_emb=(const float*)p; break;        // [A,CE]
            case 72:      Wc=(const float*)p; break;              // [Lf,K*CE]
            case 4:       bc=(const float*)p; break;              // [Lf]
            case 336:     if(!Wih_f) Wih_f=(const float*)p; else Wih_b=(const float*)p; break;
            case 144:     if(!Whh_f) Whh_f=(const float*)p; else Whh_b=(const float*)p; break;
            case 24:      if(!b_f)   b_f  =(const float*)p; else b_b  =(const float*)p; break;
            case 1620:    Wt=(const float*)p; break;              // [T,2H]
            case 135:     bt=(const float*)p; break;              // [T]
        }
    }

    k1_embed<<<NW/256, 256>>>(word_idx, char_idx, word_emb, char_emb,
                              Wc, bc, Wih_f, b_f, Wih_b, b_b);
    k2_lstm<<<(2*Bsz*32)/256, 256>>>(Whh_f, Whh_b);   // 2048 warps
    k3_tag<<<NW/128, 256>>>(Wt, bt, (float*)d_out);
    (void)out_size; (void)n_in;
}